// round 7
// baseline (speedup 1.0000x reference)
#include <cuda_runtime.h>
#include <cuda_fp16.h>
#include <cstdint>
#include <cstddef>

// ---------------------------------------------------------------------------
// RyeElman, round 6: fp16 mma.sync m16n8k16, m32/warp, B table in SMEM.
//
//   proj[h] = sum_{c<=c'} Mn[c,c'] * G[(c,c'),h]   (Gram factorization)
//   One GEMM: A[B x 352] @ Wbig[352 x 144]  (fp16 in, fp32 accum)
//   512 threads / 128 rows per block; warps 4(M) x 4(N); each warp m32.
//   B operands pre-packed fragment-major in d_WB, copied to smem per block.
// ---------------------------------------------------------------------------

#define BDIM  512
#define ROWSB 128
#define KD    192
#define NPAIR 153
#define NKS   22                 // 352 / 16
#define ASTR  368                // halves per A row

// trimmed fragment table: per k-step 1152 uint32:
//   colW<3 : off = colW*320 + lane*10 + reg,  reg<10: tile=reg>>1, bsel=reg&1
//   colW==3: off = 960      + lane*6  + reg,  reg<6
#define TBL_STEP 1152
#define TBL_TOT  (NKS * TBL_STEP)            // 25344 uint32 = 101.4 KB
__device__ __align__(16) uint32_t d_WB[TBL_TOT];

// smem float offsets
#define SF_BII  0                 // 128
#define SF_WEE  128               // 272
#define SF_SLOT 400               // 16 warps * 272 = 4352 (Gram) ; Gs alias (2048)
#define SF_TBL  4752              // 25344 uint32 (byte 19008, 16-aligned)
#define SF_A    30096             // 128*368 halves = 23552 floats (byte 120384)
#define SF_TOTAL (SF_A + ROWSB * ASTR / 2)   // 53648 floats = 214592 B

__device__ __forceinline__ void mma_f16(float* c, uint32_t a0, uint32_t a1,
                                        uint32_t a2, uint32_t a3,
                                        uint32_t b0, uint32_t b1) {
    asm volatile(
        "mma.sync.aligned.m16n8k16.row.col.f32.f16.f16.f32 "
        "{%0,%1,%2,%3}, {%4,%5,%6,%7}, {%8,%9}, {%0,%1,%2,%3};"
        : "+f"(c[0]), "+f"(c[1]), "+f"(c[2]), "+f"(c[3])
        : "r"(a0), "r"(a1), "r"(a2), "r"(a3), "r"(b0), "r"(b1));
}

// pair-permuted A column layout (same as R5, verified passing)
__device__ __forceinline__ int pair_off(int k) {          // k even
    int group = k >> 4, p = (k >> 1) & 7;
    int ppos = ((p & 3) << 1) | (p >> 2);
    return group * 16 + ppos * 2;
}
__device__ __forceinline__ int elem_off(int k) {
    return pair_off(k & ~1) + (k & 1);
}

__device__ __forceinline__ float tanh_ap(float x) {
    float y;
    asm("tanh.approx.f32 %0, %1;" : "=f"(y) : "f"(x));
    return y;
}

// ---------------------------------------------------------------------------
// K0: build trimmed fragment-major fp16 table.
// ---------------------------------------------------------------------------
__device__ __forceinline__ float wbig_val(int k, int n,
                                          const float* Wii, const float* Wdamp,
                                          const float* Wl,  const float* Wr) {
    if (k < KD) return (n < 128) ? Wii[k * 128 + n] : Wdamp[k * 16 + (n - 128)];
    if (k < KD + NPAIR && n < 128) {
        int p = k - KD, c = 0, rem = p;
        while (rem >= 17 - c) { rem -= 17 - c; c++; }
        int c2 = c + rem;
        float g = Wl[c * 128 + n] * Wr[c2 * 128 + n];
        if (c2 != c) g += Wl[c2 * 128 + n] * Wr[c * 128 + n];
        return g;
    }
    return 0.f;
}

__global__ void prep_w_kernel(const float* __restrict__ Wii,
                              const float* __restrict__ Wdamp,
                              const float* __restrict__ Wl,
                              const float* __restrict__ Wr) {
    int idx = blockIdx.x * blockDim.x + threadIdx.x;
    if (idx >= TBL_TOT) return;
    int t = idx / TBL_STEP, off = idx - t * TBL_STEP;
    int colW, lane, reg;
    if (off < 960) { colW = off / 320; int rm = off - colW * 320; lane = rm / 10; reg = rm - lane * 10; }
    else           { colW = 3;         int rm = off - 960;        lane = rm / 6;  reg = rm - lane * 6; }
    int tile = reg >> 1, bsel = reg & 1;
    int n = colW * 40 + tile * 8 + (lane >> 2);
    int k = t * 16 + 2 * (lane & 3) + bsel * 8;
    float v0 = wbig_val(k, n, Wii, Wdamp, Wl, Wr);
    float v1 = wbig_val(k + 1, n, Wii, Wdamp, Wl, Wr);
    __half2 h = __floats2half2_rn(v0, v1);
    d_WB[idx] = *reinterpret_cast<uint32_t*>(&h);
}

// ---------------------------------------------------------------------------
// GEMM inner loop: m32 x (NT*8) per warp, operands dual-buffered from smem.
// ---------------------------------------------------------------------------
template<int NT>
__device__ __forceinline__ void do_gemm(const __half* Ar0, const uint32_t* Bp,
                                        float (*acc)[4]) {
    uint2 b[2][NT]; uint2 a[2][4];
#pragma unroll
    for (int i = 0; i < NT; i++) b[0][i] = *reinterpret_cast<const uint2*>(Bp + 2 * i);
#pragma unroll
    for (int j = 0; j < 4; j++) a[0][j] = *reinterpret_cast<const uint2*>(Ar0 + j * 8 * ASTR);
#pragma unroll
    for (int t = 0; t < NKS; t++) {
        int cur = t & 1, nx = cur ^ 1;
        if (t < NKS - 1) {
            const uint32_t* bp = Bp + (t + 1) * TBL_STEP;
#pragma unroll
            for (int i = 0; i < NT; i++) b[nx][i] = *reinterpret_cast<const uint2*>(bp + 2 * i);
            const __half* ap = Ar0 + (t + 1) * 16;
#pragma unroll
            for (int j = 0; j < 4; j++) a[nx][j] = *reinterpret_cast<const uint2*>(ap + j * 8 * ASTR);
        }
#pragma unroll
        for (int mi = 0; mi < 2; mi++)
#pragma unroll
            for (int nt = 0; nt < NT; nt++)
                mma_f16(acc[mi * NT + nt],
                        a[cur][mi * 2].x, a[cur][mi * 2 + 1].x,
                        a[cur][mi * 2].y, a[cur][mi * 2 + 1].y,
                        b[cur][nt].x, b[cur][nt].y);
    }
}

// ---------------------------------------------------------------------------
// K1: fused main kernel.
// ---------------------------------------------------------------------------
__global__ __launch_bounds__(BDIM, 1)
void rye_main(const float* __restrict__ invi, const float* __restrict__ eqi,
              const float* __restrict__ invh, const float* __restrict__ eqh,
              const float* __restrict__ bii,  const float* __restrict__ Wee,
              float* __restrict__ out, int Btot) {
    extern __shared__ float smf[];
    __half*   As = reinterpret_cast<__half*>(smf + SF_A);
    uint32_t* Tb = reinterpret_cast<uint32_t*>(smf + SF_TBL);

    int tid = threadIdx.x, wid = tid >> 5, lane = tid & 31;
    size_t row0 = (size_t)blockIdx.x * ROWSB;

    // ---- table copy (global, L2-hot -> smem) ----
    {
        const uint4* src = reinterpret_cast<const uint4*>(d_WB);
        uint4* dst = reinterpret_cast<uint4*>(Tb);
        for (int i = tid; i < TBL_TOT / 4; i += BDIM) dst[i] = src[i];
    }
    if (tid < 128) smf[SF_BII + tid] = bii[tid];
    if (tid < 272) smf[SF_WEE + tid] = Wee[tid];

    // ---- stage A invariant region (cols 0..191, pair-permuted fp16) ----
    for (int t = tid; t < ROWSB * 16; t += BDIM) {           // invi -> k [0,64)
        int r = t >> 4, q = t & 15, k0 = q * 4;
        float4 v = __ldcs(reinterpret_cast<const float4*>(invi + (row0 + r) * 64) + q);
        __half2 h0 = __floats2half2_rn(v.x, v.y), h1 = __floats2half2_rn(v.z, v.w);
        __half* Ar = As + r * ASTR;
        *reinterpret_cast<__half2*>(Ar + pair_off(k0))     = h0;
        *reinterpret_cast<__half2*>(Ar + pair_off(k0 + 2)) = h1;
    }
    for (int t = tid; t < ROWSB * 32; t += BDIM) {           // invh -> k [64,192)
        int r = t >> 5, q = t & 31, k0 = 64 + q * 4;
        float4 v = __ldcs(reinterpret_cast<const float4*>(invh + (row0 + r) * 128) + q);
        __half2 h0 = __floats2half2_rn(v.x, v.y), h1 = __floats2half2_rn(v.z, v.w);
        __half* Ar = As + r * ASTR;
        *reinterpret_cast<__half2*>(Ar + pair_off(k0))     = h0;
        *reinterpret_cast<__half2*>(Ar + pair_off(k0 + 2)) = h1;
    }
    for (int t = tid; t < ROWSB * 3; t += BDIM) {            // zero k [346,352)
        int r = t / 3, j = t - r * 3;
        __half2 z; z.x = __ushort_as_half(0); z.y = __ushort_as_half(0);
        *reinterpret_cast<__half2*>(As + r * ASTR + pair_off(346 + 2 * j)) = z;
    }

    // ---- Gram: per-warp 4-row slots, writes A cols [192,346) ----
    {
        float* slot = smf + SF_SLOT + wid * 272;             // 4 rows x 68 floats
        for (int it = 0; it < 2; it++) {
            int rbase = it * 64 + wid * 4;
            for (int j = lane; j < 192; j += 32) {           // eqh, coalesced
                int d = j / 48, q = j - d * 48;
                int s = q >> 4, c = q & 15;
                slot[d * 68 + s * 17 + 1 + c] = eqh[(row0 + rbase) * 48 + j];
            }
            if (lane < 12) {                                  // eqi
                int d = lane / 3, s = lane - d * 3;
                slot[d * 68 + s * 17] = eqi[(row0 + rbase) * 3 + lane];
            }
            __syncwarp();
            for (int j = lane; j < 68; j += 32) {             // 1/norm
                int d = j / 17, c = j - d * 17;
                float* S = slot + d * 68;
                float e0 = S[c], e1 = S[17 + c], e2 = S[34 + c];
                S[51 + c] = __frcp_rn(fmaf(e0, e0, fmaf(e1, e1, fmaf(e2, e2, 1e-6f))));
            }
            __syncwarp();
            {
                int d = lane >> 3, sub = lane & 7;
                const float* S  = slot + d * 68;
                const float* IN = S + 51;
                __half* Ar = As + (rbase + d) * ASTR;
#pragma unroll
                for (int cs = 0; cs < 2; cs++) {
                    int c = sub + cs * 8;
                    float e0 = S[c], e1 = S[17 + c], e2 = S[34 + c];
                    float ic = IN[c];
                    int pbase = c * 17 - (c * (c - 1)) / 2 - c;
                    for (int c2 = c; c2 < 17; c2++) {
                        float g = fmaf(e0, S[c2], fmaf(e1, S[17 + c2], e2 * S[34 + c2]));
                        Ar[elem_off(KD + pbase + c2)] = __float2half(g * ic * IN[c2]);
                    }
                }
                if (sub == 0) {                               // (16,16) + pad 345
                    float g = fmaf(S[16], S[16], fmaf(S[33], S[33], S[50] * S[50]));
                    __half2 h = __floats2half2_rn(g * IN[16] * IN[16], 0.f);
                    *reinterpret_cast<__half2*>(Ar + pair_off(344)) = h;
                }
            }
            __syncwarp();
        }
    }
    __syncthreads();

    // ---- GEMM + epilogue ----
    int mw = wid >> 2, colW = wid & 3;
    int m0 = mw * 32;
    int g = lane >> 2, t4 = lane & 3;
    const __half* Ar0 = As + (m0 + g) * ASTR + t4 * 4;
    float* Gs = smf + SF_SLOT;                                // alias post-GEMM

    if (colW < 3) {
        const uint32_t* Bp = Tb + colW * 320 + lane * 10;
        float acc[10][4];
#pragma unroll
        for (int i = 0; i < 10; i++) acc[i][0] = acc[i][1] = acc[i][2] = acc[i][3] = 0.f;
        do_gemm<5>(Ar0, Bp, acc);
#pragma unroll
        for (int mi = 0; mi < 2; mi++) {
            int lr = m0 + mi * 16 + g;
            float* o0 = out + (row0 + lr) * 128;
            float* o1 = out + (row0 + lr + 8) * 128;
#pragma unroll
            for (int nt = 0; nt < 5; nt++) {
                int j = colW * 40 + nt * 8 + 2 * t4;
                float b0 = smf[SF_BII + j], b1 = smf[SF_BII + j + 1];
                float2 v0 = make_float2(tanh_ap(acc[mi * 5 + nt][0] + b0),
                                        tanh_ap(acc[mi * 5 + nt][1] + b1));
                float2 v1 = make_float2(tanh_ap(acc[mi * 5 + nt][2] + b0),
                                        tanh_ap(acc[mi * 5 + nt][3] + b1));
                *reinterpret_cast<float2*>(o0 + j) = v0;
                *reinterpret_cast<float2*>(o1 + j) = v1;
            }
        }
    } else {
        const uint32_t* Bp = Tb + 960 + lane * 6;
        float acc[6][4];
#pragma unroll
        for (int i = 0; i < 6; i++) acc[i][0] = acc[i][1] = acc[i][2] = acc[i][3] = 0.f;
        do_gemm<3>(Ar0, Bp, acc);
#pragma unroll
        for (int mi = 0; mi < 2; mi++) {
            int lr = m0 + mi * 16 + g;
            {   // nt=0 -> cols 120..127 (tanh)
                int j = 120 + 2 * t4;
                float b0 = smf[SF_BII + j], b1 = smf[SF_BII + j + 1];
                float2 v0 = make_float2(tanh_ap(acc[mi * 3][0] + b0),
                                        tanh_ap(acc[mi * 3][1] + b1));
                float2 v1 = make_float2(tanh_ap(acc[mi * 3][2] + b0),
                                        tanh_ap(acc[mi * 3][3] + b1));
                *reinterpret_cast<float2*>(out + (row0 + lr) * 128 + j)     = v0;
                *reinterpret_cast<float2*>(out + (row0 + lr + 8) * 128 + j) = v1;
            }
#pragma unroll
            for (int nt = 1; nt < 3; nt++) {                  // gate cols
                int jc = (nt - 1) * 8 + 2 * t4;
                Gs[lr * 16 + jc]           = acc[mi * 3 + nt][0];
                Gs[lr * 16 + jc + 1]       = acc[mi * 3 + nt][1];
                Gs[(lr + 8) * 16 + jc]     = acc[mi * 3 + nt][2];
                Gs[(lr + 8) * 16 + jc + 1] = acc[mi * 3 + nt][3];
            }
        }
    }
    __syncthreads();

    // ---- new_equivariant: one thread per (row, s), eq data from L2 ----
    if (tid < ROWSB * 3) {
        int r = tid / 3, s = tid - r * 3;
        size_t row = row0 + r;
        const float* Wee_s = smf + SF_WEE;
        float E[17];
        E[0] = eqi[row * 3 + s];
        const float4* eh = reinterpret_cast<const float4*>(eqh + row * 48 + s * 16);
#pragma unroll
        for (int q = 0; q < 4; q++) {
            float4 v = eh[q];
            E[1 + q * 4] = v.x; E[2 + q * 4] = v.y; E[3 + q * 4] = v.z; E[4 + q * 4] = v.w;
        }
        float4 res[4];
        float* rf = reinterpret_cast<float*>(res);
#pragma unroll
        for (int c = 0; c < 16; c++) {
            float sum = 0.f;
#pragma unroll
            for (int cc = 0; cc < 17; cc++) sum = fmaf(E[cc], Wee_s[cc * 16 + c], sum);
            rf[c] = fmaf(E[1 + c], Gs[r * 16 + c], sum);
        }
        float4* dst = reinterpret_cast<float4*>(out + (size_t)Btot * 128 + row * 48 + s * 16);
        dst[0] = res[0]; dst[1] = res[1]; dst[2] = res[2]; dst[3] = res[3];
    }
}

// ---------------------------------------------------------------------------
extern "C" void kernel_launch(void* const* d_in, const int* in_sizes, int n_in,
                              void* d_out, int out_size) {
    const float* invi  = (const float*)d_in[0];
    const float* eqi   = (const float*)d_in[1];
    const float* invh  = (const float*)d_in[2];
    const float* eqhid = (const float*)d_in[3];
    const float* Wl    = (const float*)d_in[4];
    const float* Wr    = (const float*)d_in[5];
    const float* Wii   = (const float*)d_in[6];
    const float* bii   = (const float*)d_in[7];
    const float* Wee   = (const float*)d_in[8];
    const float* Wdamp = (const float*)d_in[9];
    float* out = (float*)d_out;

    int Btot = in_sizes[0] / 64;

    prep_w_kernel<<<(TBL_TOT + 255) / 256, 256>>>(Wii, Wdamp, Wl, Wr);

    int smem_bytes = SF_TOTAL * 4;
    cudaFuncSetAttribute(rye_main, cudaFuncAttributeMaxDynamicSharedMemorySize, smem_bytes);
    rye_main<<<Btot / ROWSB, BDIM, smem_bytes>>>(invi, eqi, invh, eqhid,
                                                 bii, Wee, out, Btot);
}

// round 8
// speedup vs baseline: 1.1383x; 1.1383x over previous
#include <cuda_runtime.h>
#include <cuda_fp16.h>
#include <cstdint>
#include <cstddef>

// ---------------------------------------------------------------------------
// RyeElman, round 7: fp16 mma.sync m16n8k16; 1024 thr / 128 rows / 32 warps;
// B fragment table in smem (conflict-free LDS), A panel conflict-free (ASTR=360).
//
//   proj[h] = sum_{c<=c'} Mn[c,c'] * G[(c,c'),h]   (Gram factorization)
//   One GEMM: A[B x 352] @ Wbig[352 x 144]  (fp16 in, fp32 accum)
// ---------------------------------------------------------------------------

#define BDIM  1024
#define ROWSB 128
#define KD    192
#define NPAIR 153
#define NKS   22                 // 352 / 16
#define ASTR  360                // halves per A row; 180 words -> g*20 mod 32 distinct

// trimmed fragment table: per k-step 1152 uint32:
//   colW<3 : off = colW*320 + lane*10 + reg   (reg<10: tile=reg>>1, bsel=reg&1)
//   colW==3: off = 960      + lane*6  + reg   (reg<6)
#define TBL_STEP 1152
#define TBL_TOT  (NKS * TBL_STEP)            // 25344 uint32 = 101.4 KB
__device__ __align__(16) uint32_t d_WB[TBL_TOT];

// smem float offsets
#define SF_BII  0                  // 128
#define SF_WEE  128                // 272
#define SF_GS   400                // 128*16 = 2048
#define SF_TBL  2448               // 25344 uint32 ; Gram slots alias this region
#define SF_A    27792              // 128*360 halves = 23040 floats
#define SF_TOTAL (SF_A + ROWSB * ASTR / 2)   // 50832 floats = 203328 B

__device__ __forceinline__ void mma_f16(float* c, uint32_t a0, uint32_t a1,
                                        uint32_t a2, uint32_t a3,
                                        uint32_t b0, uint32_t b1) {
    asm volatile(
        "mma.sync.aligned.m16n8k16.row.col.f32.f16.f16.f32 "
        "{%0,%1,%2,%3}, {%4,%5,%6,%7}, {%8,%9}, {%0,%1,%2,%3};"
        : "+f"(c[0]), "+f"(c[1]), "+f"(c[2]), "+f"(c[3])
        : "r"(a0), "r"(a1), "r"(a2), "r"(a3), "r"(b0), "r"(b1));
}

// pair-permuted A column layout (verified passing in R5/R6)
__device__ __forceinline__ int pair_off(int k) {          // k even
    int group = k >> 4, p = (k >> 1) & 7;
    int ppos = ((p & 3) << 1) | (p >> 2);
    return group * 16 + ppos * 2;
}
__device__ __forceinline__ int elem_off(int k) {
    return pair_off(k & ~1) + (k & 1);
}

__device__ __forceinline__ float tanh_ap(float x) {
    float y;
    asm("tanh.approx.f32 %0, %1;" : "=f"(y) : "f"(x));
    return y;
}

// ---------------------------------------------------------------------------
// K0: build trimmed fragment-major fp16 table (unchanged from R6, verified).
// ---------------------------------------------------------------------------
__device__ __forceinline__ float wbig_val(int k, int n,
                                          const float* Wii, const float* Wdamp,
                                          const float* Wl,  const float* Wr) {
    if (k < KD) return (n < 128) ? Wii[k * 128 + n] : Wdamp[k * 16 + (n - 128)];
    if (k < KD + NPAIR && n < 128) {
        int p = k - KD, c = 0, rem = p;
        while (rem >= 17 - c) { rem -= 17 - c; c++; }
        int c2 = c + rem;
        float g = Wl[c * 128 + n] * Wr[c2 * 128 + n];
        if (c2 != c) g += Wl[c2 * 128 + n] * Wr[c * 128 + n];
        return g;
    }
    return 0.f;
}

__global__ void prep_w_kernel(const float* __restrict__ Wii,
                              const float* __restrict__ Wdamp,
                              const float* __restrict__ Wl,
                              const float* __restrict__ Wr) {
    int idx = blockIdx.x * blockDim.x + threadIdx.x;
    if (idx >= TBL_TOT) return;
    int t = idx / TBL_STEP, off = idx - t * TBL_STEP;
    int colW, lane, reg;
    if (off < 960) { colW = off / 320; int rm = off - colW * 320; lane = rm / 10; reg = rm - lane * 10; }
    else           { colW = 3;         int rm = off - 960;        lane = rm / 6;  reg = rm - lane * 6; }
    int tile = reg >> 1, bsel = reg & 1;
    int n = colW * 40 + tile * 8 + (lane >> 2);
    int k = t * 16 + 2 * (lane & 3) + bsel * 8;
    float v0 = wbig_val(k, n, Wii, Wdamp, Wl, Wr);
    float v1 = wbig_val(k + 1, n, Wii, Wdamp, Wl, Wr);
    __half2 h = __floats2half2_rn(v0, v1);
    d_WB[idx] = *reinterpret_cast<uint32_t*>(&h);
}

// ---------------------------------------------------------------------------
// GEMM inner loop: m16 x (NT*8) per warp, all operands conflict-free LDS.
// ---------------------------------------------------------------------------
template<int NT>
__device__ __forceinline__ void do_gemm16(const __half* ArA, const __half* ArB,
                                          const uint32_t* Bp, float (*acc)[4]) {
#pragma unroll
    for (int t = 0; t < NKS; t++) {
        uint2 aA = *reinterpret_cast<const uint2*>(ArA + t * 16);   // row g
        uint2 aB = *reinterpret_cast<const uint2*>(ArB + t * 16);   // row g+8
        const uint32_t* bp = Bp + t * TBL_STEP;
#pragma unroll
        for (int nt = 0; nt < NT; nt++) {
            uint2 b = *reinterpret_cast<const uint2*>(bp + 2 * nt);
            mma_f16(acc[nt], aA.x, aB.x, aA.y, aB.y, b.x, b.y);
        }
    }
}

// ---------------------------------------------------------------------------
// K1: fused main kernel.
// ---------------------------------------------------------------------------
__global__ __launch_bounds__(BDIM, 1)
void rye_main(const float* __restrict__ invi, const float* __restrict__ eqi,
              const float* __restrict__ invh, const float* __restrict__ eqh,
              const float* __restrict__ bii,  const float* __restrict__ Wee,
              float* __restrict__ out, int Btot) {
    extern __shared__ float smf[];
    __half*   As = reinterpret_cast<__half*>(smf + SF_A);
    uint32_t* Tb = reinterpret_cast<uint32_t*>(smf + SF_TBL);
    float*    Gs = smf + SF_GS;

    int tid = threadIdx.x, wid = tid >> 5, lane = tid & 31;
    size_t row0 = (size_t)blockIdx.x * ROWSB;

    // ---- Phase 1: stage A invariant region + consts ----
    if (tid < 128) smf[SF_BII + tid] = bii[tid];
    if (tid < 272) smf[SF_WEE + tid] = Wee[tid];
    for (int t = tid; t < ROWSB * 16; t += BDIM) {           // invi -> k [0,64)
        int r = t >> 4, q = t & 15, k0 = q * 4;
        float4 v = reinterpret_cast<const float4*>(invi + (row0 + r) * 64)[q];
        __half2 h0 = __floats2half2_rn(v.x, v.y), h1 = __floats2half2_rn(v.z, v.w);
        __half* Ar = As + r * ASTR;
        *reinterpret_cast<__half2*>(Ar + pair_off(k0))     = h0;
        *reinterpret_cast<__half2*>(Ar + pair_off(k0 + 2)) = h1;
    }
    for (int t = tid; t < ROWSB * 32; t += BDIM) {           // invh -> k [64,192)
        int r = t >> 5, q = t & 31, k0 = 64 + q * 4;
        float4 v = reinterpret_cast<const float4*>(invh + (row0 + r) * 128)[q];
        __half2 h0 = __floats2half2_rn(v.x, v.y), h1 = __floats2half2_rn(v.z, v.w);
        __half* Ar = As + r * ASTR;
        *reinterpret_cast<__half2*>(Ar + pair_off(k0))     = h0;
        *reinterpret_cast<__half2*>(Ar + pair_off(k0 + 2)) = h1;
    }
    for (int t = tid; t < ROWSB * 3; t += BDIM) {            // zero k [346,352)
        int r = t / 3, j = t - r * 3;
        __half2 z; z.x = __ushort_as_half(0); z.y = __ushort_as_half(0);
        *reinterpret_cast<__half2*>(As + r * ASTR + pair_off(346 + 2 * j)) = z;
    }

    // ---- Phase 2: Gram -> A cols [192,346). 32 warps x 4 rows, one pass.
    //      Slots live in the (not yet filled) table region.
    {
        float* slot = smf + SF_TBL + wid * 272;              // 4 rows x 68 floats
        int rbase = wid * 4;
        for (int j = lane; j < 192; j += 32) {               // eqh, coalesced
            int d = j / 48, q = j - d * 48;
            int s = q >> 4, c = q & 15;
            slot[d * 68 + s * 17 + 1 + c] = eqh[(row0 + rbase) * 48 + j];
        }
        if (lane < 12) {                                     // eqi
            int d = lane / 3, s = lane - d * 3;
            slot[d * 68 + s * 17] = eqi[(row0 + rbase) * 3 + lane];
        }
        __syncwarp();
        for (int j = lane; j < 68; j += 32) {                // 1/norm
            int d = j / 17, c = j - d * 17;
            float* S = slot + d * 68;
            float e0 = S[c], e1 = S[17 + c], e2 = S[34 + c];
            S[51 + c] = __frcp_rn(fmaf(e0, e0, fmaf(e1, e1, fmaf(e2, e2, 1e-6f))));
        }
        __syncwarp();
        {
            int d = lane >> 3, sub = lane & 7;
            const float* S  = slot + d * 68;
            const float* IN = S + 51;
            __half* Ar = As + (rbase + d) * ASTR;
#pragma unroll
            for (int cs = 0; cs < 2; cs++) {
                int c = sub + cs * 8;
                float e0 = S[c], e1 = S[17 + c], e2 = S[34 + c];
                float ic = IN[c];
                int pbase = c * 17 - (c * (c - 1)) / 2 - c;
                for (int c2 = c; c2 < 17; c2++) {
                    float g = fmaf(e0, S[c2], fmaf(e1, S[17 + c2], e2 * S[34 + c2]));
                    Ar[elem_off(KD + pbase + c2)] = __float2half(g * ic * IN[c2]);
                }
            }
            if (sub == 0) {                                  // (16,16) + zero pad 345
                float g = fmaf(S[16], S[16], fmaf(S[33], S[33], S[50] * S[50]));
                __half2 h = __floats2half2_rn(g * IN[16] * IN[16], 0.f);
                *reinterpret_cast<__half2*>(Ar + pair_off(344)) = h;
            }
        }
    }
    __syncthreads();                                         // Gram done, slots free

    // ---- Phase 3: copy fragment table into smem (overwrites slots) ----
    {
        const uint4* src = reinterpret_cast<const uint4*>(d_WB);
        uint4* dst = reinterpret_cast<uint4*>(Tb);
        for (int i = tid; i < TBL_TOT / 4; i += BDIM) dst[i] = src[i];
    }
    __syncthreads();

    // ---- Phase 4: GEMM + epilogue ----
    int mw = wid >> 2, colW = wid & 3;
    int m0 = mw * 16;
    int g = lane >> 2, t4 = lane & 3;
    const __half* ArA = As + (m0 + g) * ASTR + t4 * 4;
    const __half* ArB = ArA + 8 * ASTR;

    if (colW < 3) {
        const uint32_t* Bp = Tb + colW * 320 + lane * 10;
        float acc[5][4];
#pragma unroll
        for (int i = 0; i < 5; i++) acc[i][0] = acc[i][1] = acc[i][2] = acc[i][3] = 0.f;
        do_gemm16<5>(ArA, ArB, Bp, acc);
        int lr = m0 + g;
        float* o0 = out + (row0 + lr) * 128;
        float* o1 = out + (row0 + lr + 8) * 128;
#pragma unroll
        for (int nt = 0; nt < 5; nt++) {
            int j = colW * 40 + nt * 8 + 2 * t4;
            float b0 = smf[SF_BII + j], b1 = smf[SF_BII + j + 1];
            float2 v0 = make_float2(tanh_ap(acc[nt][0] + b0), tanh_ap(acc[nt][1] + b1));
            float2 v1 = make_float2(tanh_ap(acc[nt][2] + b0), tanh_ap(acc[nt][3] + b1));
            *reinterpret_cast<float2*>(o0 + j) = v0;
            *reinterpret_cast<float2*>(o1 + j) = v1;
        }
    } else {
        const uint32_t* Bp = Tb + 960 + lane * 6;
        float acc[3][4];
#pragma unroll
        for (int i = 0; i < 3; i++) acc[i][0] = acc[i][1] = acc[i][2] = acc[i][3] = 0.f;
        do_gemm16<3>(ArA, ArB, Bp, acc);
        int lr = m0 + g;
        {   // nt=0 -> cols 120..127 (tanh)
            int j = 120 + 2 * t4;
            float b0 = smf[SF_BII + j], b1 = smf[SF_BII + j + 1];
            float2 v0 = make_float2(tanh_ap(acc[0][0] + b0), tanh_ap(acc[0][1] + b1));
            float2 v1 = make_float2(tanh_ap(acc[0][2] + b0), tanh_ap(acc[0][3] + b1));
            *reinterpret_cast<float2*>(out + (row0 + lr) * 128 + j)     = v0;
            *reinterpret_cast<float2*>(out + (row0 + lr + 8) * 128 + j) = v1;
        }
#pragma unroll
        for (int nt = 1; nt < 3; nt++) {                     // gate cols 128..143
            int jc = (nt - 1) * 8 + 2 * t4;
            Gs[lr * 16 + jc]           = acc[nt][0];
            Gs[lr * 16 + jc + 1]       = acc[nt][1];
            Gs[(lr + 8) * 16 + jc]     = acc[nt][2];
            Gs[(lr + 8) * 16 + jc + 1] = acc[nt][3];
        }
    }
    __syncthreads();

    // ---- new_equivariant: one thread per (row, s), eq data from L2 ----
    if (tid < ROWSB * 3) {
        int r = tid / 3, s = tid - r * 3;
        size_t row = row0 + r;
        const float* Wee_s = smf + SF_WEE;
        float E[17];
        E[0] = eqi[row * 3 + s];
        const float4* eh = reinterpret_cast<const float4*>(eqh + row * 48 + s * 16);
#pragma unroll
        for (int q = 0; q < 4; q++) {
            float4 v = eh[q];
            E[1 + q * 4] = v.x; E[2 + q * 4] = v.y; E[3 + q * 4] = v.z; E[4 + q * 4] = v.w;
        }
        float4 res[4];
        float* rf = reinterpret_cast<float*>(res);
#pragma unroll
        for (int c = 0; c < 16; c++) {
            float sum = 0.f;
#pragma unroll
            for (int cc = 0; cc < 17; cc++) sum = fmaf(E[cc], Wee_s[cc * 16 + c], sum);
            rf[c] = fmaf(E[1 + c], Gs[r * 16 + c], sum);
        }
        float4* dst = reinterpret_cast<float4*>(out + (size_t)Btot * 128 + row * 48 + s * 16);
        dst[0] = res[0]; dst[1] = res[1]; dst[2] = res[2]; dst[3] = res[3];
    }
}

// ---------------------------------------------------------------------------
extern "C" void kernel_launch(void* const* d_in, const int* in_sizes, int n_in,
                              void* d_out, int out_size) {
    const float* invi  = (const float*)d_in[0];
    const float* eqi   = (const float*)d_in[1];
    const float* invh  = (const float*)d_in[2];
    const float* eqhid = (const float*)d_in[3];
    const float* Wl    = (const float*)d_in[4];
    const float* Wr    = (const float*)d_in[5];
    const float* Wii   = (const float*)d_in[6];
    const float* bii   = (const float*)d_in[7];
    const float* Wee   = (const float*)d_in[8];
    const float* Wdamp = (const float*)d_in[9];
    float* out = (float*)d_out;

    int Btot = in_sizes[0] / 64;

    prep_w_kernel<<<(TBL_TOT + 255) / 256, 256>>>(Wii, Wdamp, Wl, Wr);

    int smem_bytes = SF_TOTAL * 4;
    cudaFuncSetAttribute(rye_main, cudaFuncAttributeMaxDynamicSharedMemorySize, smem_bytes);
    rye_main<<<Btot / ROWSB, BDIM, smem_bytes>>>(invi, eqi, invh, eqhid,
                                                 bii, Wee, out, Btot);
}